// round 6
// baseline (speedup 1.0000x reference)
#include <cuda_runtime.h>

// ---------------------------------------------------------------------------
// SymmetricContraction: out[b,c,m] = cubic polynomial in A[b,c,0..8]
// Stage 1 (prep):  S[c][t][m] = sum_k Usym[t][m][k] * w_k[c]
// Stage 2 (trA):   A[b][c][9] -> At[c][b][12]   (flat-word coalesced tiles)
// Stage 3 (main):  Ot[c][b][12] = sum_t S[c][t][:] * mono_t(At[c][b][:])
// Stage 4 (trO):   Ot[c][b][12] -> out[b][c][9] (flat-word coalesced tiles)
// ---------------------------------------------------------------------------

#define NC 128        // channels
#define NB 2048       // nodes
#define NI 9          // irreps dim
#define NIP 12        // padded per-node vector (48B)
#define NT 219        // 9 singles + 45 pairs + 165 triples
#define ROWP 12       // padded S row (floats) -> 48B
#define NBT 2         // nodes per thread
#define BLK 128       // threads per main block

#define NROW2 (45 * 9)
#define NROW3 (165 * 9)
#define NROWS (9 + NROW2 + NROW3)   // 1899 job rows

#define TAB 8                  // b-rows per transpose block
#define TROW (NC * NI)         // 1152 words per b-row
#define TPAD 1153              // odd smem row stride (bank-conflict-free)

static __device__ float g_S[NC * NT * ROWP];          // ~1.35 MB
static __device__ float g_At[NC * NB * NIP];          // 12.6 MB
static __device__ float g_Ot[NC * NB * NIP];          // 12.6 MB

// ---------------------------------------------------------------------------
// Kernel 1: fused prep (unchanged — verified)
// ---------------------------------------------------------------------------
__global__ void prep_kernel(
    const float* __restrict__ Us1, const float* __restrict__ Up1, const float* __restrict__ Ud1,
    const float* __restrict__ Us2, const float* __restrict__ Up2, const float* __restrict__ Ud2,
    const float* __restrict__ Us3, const float* __restrict__ Up3, const float* __restrict__ Ud3,
    const float* __restrict__ ws1, const float* __restrict__ ws2, const float* __restrict__ ws3,
    const float* __restrict__ wp1, const float* __restrict__ wp2, const float* __restrict__ wp3,
    const float* __restrict__ wd1, const float* __restrict__ wd2, const float* __restrict__ wd3)
{
    int gid = blockIdx.x * blockDim.x + threadIdx.x;
    if (gid >= NROWS * NC) return;
    int c = gid % NC;
    int row = gid / NC;

    if (row < 9) {
        int t = row;
        float* dst = g_S + (c * NT + t) * ROWP;
        dst[0] = Us1[t] * ws1[c];
#pragma unroll
        for (int m = 0; m < 3; m++) dst[1 + m] = Up1[m * 9 + t] * wp1[c];
#pragma unroll
        for (int m = 0; m < 5; m++) dst[4 + m] = Ud1[m * 9 + t] * wd1[c];
        dst[9] = 0.f; dst[10] = 0.f; dst[11] = 0.f;
        return;
    }

    if (row < 9 + NROW2) {
        int r = row - 9;
        int m = r % 9, tp = r / 9;
        int t = 9 + tp;
        int rem = tp, i = 0, j = 0;
        for (i = 0; i < 9; i++) { int cnt = 9 - i; if (rem < cnt) { j = i + rem; break; } rem -= cnt; }
        float inv = (i == j) ? 0.5f : 1.0f;

        int K; const float* U; const float* w; int mm;
        if (m == 0)      { K = 2; U = Us2; w = ws2; mm = 0; }
        else if (m < 4)  { K = 3; U = Up2; w = wp2; mm = m - 1; }
        else             { K = 4; U = Ud2; w = wd2; mm = m - 4; }

        float s = 0.f;
        for (int k = 0; k < K; k++) {
            float u = U[((mm * 9 + i) * 9 + j) * K + k] + U[((mm * 9 + j) * 9 + i) * K + k];
            s += u * w[k * NC + c];
        }
        float* dst = g_S + (c * NT + t) * ROWP;
        dst[m] = s * inv;
        if (m < 3) dst[9 + m] = 0.f;
        return;
    }

    {
        int r = row - (9 + NROW2);
        int m = r % 9, tp = r / 9;
        int t = 54 + tp;
        int rem = tp, i = 0, j = 0, l = 0;
        for (i = 0; i < 9; i++) { int cnt = (9 - i) * (10 - i) / 2; if (rem < cnt) break; rem -= cnt; }
        for (j = i; j < 9; j++) { int cnt = 9 - j; if (rem < cnt) { l = j + rem; break; } rem -= cnt; }
        float inv;
        if (i == j && j == l)                 inv = 1.0f / 6.0f;
        else if (i == j || j == l || i == l)  inv = 0.5f;
        else                                  inv = 1.0f;

        int K; const float* U; const float* w; int mm;
        if (m == 0)      { K = 5;  U = Us3; w = ws3; mm = 0; }
        else if (m < 4)  { K = 8;  U = Up3; w = wp3; mm = m - 1; }
        else             { K = 10; U = Ud3; w = wd3; mm = m - 4; }

        int P0[6] = { i,i,j,j,l,l }, P1[6] = { j,l,i,l,i,j }, P2i[6] = { l,j,l,i,j,i };
        float s = 0.f;
        for (int k = 0; k < K; k++) {
            float u = 0.f;
#pragma unroll
            for (int p = 0; p < 6; p++)
                u += U[(((mm * 9 + P0[p]) * 9 + P1[p]) * 9 + P2i[p]) * K + k];
            s += u * w[k * NC + c];
        }
        float* dst = g_S + (c * NT + t) * ROWP;
        dst[m] = s * inv;
        if (m < 3) dst[9 + m] = 0.f;
    }
}

// ---------------------------------------------------------------------------
// Kernel 2: A [b][c][9] -> At [c][b][12].
// Read side: 8 b-rows of 4608 contiguous bytes, flat word loop (coalesced).
// Write side: per-c chunks of 8*12 contiguous words (coalesced).
// ---------------------------------------------------------------------------
__global__ __launch_bounds__(256) void transposeA_kernel(const float* __restrict__ A)
{
    __shared__ float tile[TAB * TPAD];
    int b0 = blockIdx.x * TAB;

    // Phase 1: flat coalesced read of 8 contiguous b-rows.
#pragma unroll
    for (int w = threadIdx.x; w < TAB * TROW; w += 256) {
        int b = w / TROW, r = w % TROW;         // r = c*9 + i
        tile[b * TPAD + r] = A[(b0 + b) * TROW + r];
    }
    __syncthreads();

    // Phase 2: flat coalesced write, per-c chunks of TAB*12 words.
#pragma unroll
    for (int w = threadIdx.x; w < NC * TAB * NIP; w += 256) {
        int c = w / (TAB * NIP), v = w % (TAB * NIP);
        int b = v / NIP, i = v % NIP;
        float val = (i < NI) ? tile[b * TPAD + c * NI + i] : 0.f;
        g_At[(c * NB + b0) * NIP + v] = val;
    }
}

// ---------------------------------------------------------------------------
// Kernel 3: hot loop (unchanged from R5 — verified fast).
// ---------------------------------------------------------------------------
__device__ __forceinline__ void fma9xN(float acc[NBT][9], const float* __restrict__ row,
                                       const float mN[NBT])
{
    float4 r0 = *reinterpret_cast<const float4*>(row);
    float4 r1 = *reinterpret_cast<const float4*>(row + 4);
    float  r8 = row[8];
#pragma unroll
    for (int n = 0; n < NBT; n++) {
        acc[n][0] = fmaf(r0.x, mN[n], acc[n][0]);
        acc[n][1] = fmaf(r0.y, mN[n], acc[n][1]);
        acc[n][2] = fmaf(r0.z, mN[n], acc[n][2]);
        acc[n][3] = fmaf(r0.w, mN[n], acc[n][3]);
        acc[n][4] = fmaf(r1.x, mN[n], acc[n][4]);
        acc[n][5] = fmaf(r1.y, mN[n], acc[n][5]);
        acc[n][6] = fmaf(r1.z, mN[n], acc[n][6]);
        acc[n][7] = fmaf(r1.w, mN[n], acc[n][7]);
        acc[n][8] = fmaf(r8,  mN[n], acc[n][8]);
    }
}

__global__ __launch_bounds__(BLK) void sc_main_kernel()
{
    __shared__ __align__(16) float sS[NT * ROWP];

    int c = blockIdx.x;
    const float* gS = g_S + c * NT * ROWP;
    for (int idx = threadIdx.x; idx < NT * ROWP; idx += BLK)
        sS[idx] = gS[idx];
    __syncthreads();

    int bbase = blockIdx.y * (BLK * NBT) + threadIdx.x;

    float a[NBT][9];
#pragma unroll
    for (int n = 0; n < NBT; n++) {
        const float4* Ap = reinterpret_cast<const float4*>(
            g_At + (c * NB + bbase + n * BLK) * NIP);
        float4 v0 = Ap[0], v1 = Ap[1], v2 = Ap[2];
        a[n][0] = v0.x; a[n][1] = v0.y; a[n][2] = v0.z; a[n][3] = v0.w;
        a[n][4] = v1.x; a[n][5] = v1.y; a[n][6] = v1.z; a[n][7] = v1.w;
        a[n][8] = v2.x;
    }

    float acc[NBT][9];
#pragma unroll
    for (int n = 0; n < NBT; n++)
#pragma unroll
        for (int q = 0; q < 9; q++) acc[n][q] = 0.f;

#pragma unroll
    for (int i = 0; i < 9; i++) {
        float mN[NBT];
#pragma unroll
        for (int n = 0; n < NBT; n++) mN[n] = a[n][i];
        fma9xN(acc, sS + i * ROWP, mN);
    }

    int trow = 54;
#pragma unroll
    for (int i = 0; i < 9; i++) {
#pragma unroll
        for (int j = i; j < 9; j++) {
            int pidx = i * 9 - (i * (i - 1)) / 2 + (j - i);
            float pN[NBT];
#pragma unroll
            for (int n = 0; n < NBT; n++) pN[n] = a[n][i] * a[n][j];
            fma9xN(acc, sS + (9 + pidx) * ROWP, pN);
#pragma unroll
            for (int l = j; l < 9; l++) {
                float mN[NBT];
#pragma unroll
                for (int n = 0; n < NBT; n++) mN[n] = pN[n] * a[n][l];
                fma9xN(acc, sS + trow * ROWP, mN);
                trow++;
            }
        }
    }

#pragma unroll
    for (int n = 0; n < NBT; n++) {
        float4* op = reinterpret_cast<float4*>(
            g_Ot + (c * NB + bbase + n * BLK) * NIP);
        op[0] = make_float4(acc[n][0], acc[n][1], acc[n][2], acc[n][3]);
        op[1] = make_float4(acc[n][4], acc[n][5], acc[n][6], acc[n][7]);
        op[2] = make_float4(acc[n][8], 0.f, 0.f, 0.f);
    }
}

// ---------------------------------------------------------------------------
// Kernel 4: Ot [c][b][12] -> out [b][c][9]. Mirror of transposeA.
// ---------------------------------------------------------------------------
__global__ __launch_bounds__(256) void transposeO_kernel(float* __restrict__ out)
{
    __shared__ float tile[TAB * TPAD];
    int b0 = blockIdx.x * TAB;

    // Phase 1: flat coalesced read, per-c chunks of TAB*12 words.
#pragma unroll
    for (int w = threadIdx.x; w < NC * TAB * NIP; w += 256) {
        int c = w / (TAB * NIP), v = w % (TAB * NIP);
        int b = v / NIP, i = v % NIP;
        float val = g_Ot[(c * NB + b0) * NIP + v];
        if (i < NI) tile[b * TPAD + c * NI + i] = val;
    }
    __syncthreads();

    // Phase 2: flat coalesced write of 8 contiguous b-rows.
#pragma unroll
    for (int w = threadIdx.x; w < TAB * TROW; w += 256) {
        int b = w / TROW, r = w % TROW;
        out[(b0 + b) * TROW + r] = tile[b * TPAD + r];
    }
}

// ---------------------------------------------------------------------------
// Launch
// ---------------------------------------------------------------------------
extern "C" void kernel_launch(void* const* d_in, const int* in_sizes, int n_in,
                              void* d_out, int out_size)
{
    const float* A = nullptr;
    const float* U[3][3] = {};
    const float* W[3][3] = {};

    int typeorder[3] = { 0, 1, 2 };
    int to_n = 0;
    int w1_idx[3]; int w1_n = 0;

    for (int idx = 0; idx < n_in; idx++) {
        int s = in_sizes[idx];
        const float* p = (const float*)d_in[idx];
        switch (s) {
            case NB * NC * NI: A = p; break;
            case 9:     U[0][0] = p; break;
            case 162:   U[0][1] = p; break;
            case 3645:  U[0][2] = p; break;
            case 27:    U[1][0] = p; break;
            case 729:   U[1][1] = p; break;
            case 17496: U[1][2] = p; break;
            case 45:    U[2][0] = p; break;
            case 1620:  U[2][1] = p; break;
            case 36450: U[2][2] = p; break;
            case 256:   W[0][1] = p; if (to_n < 3) typeorder[to_n++] = 0; break;
            case 384:   W[1][1] = p; if (to_n < 3) typeorder[to_n++] = 1; break;
            case 512:   W[2][1] = p; if (to_n < 3) typeorder[to_n++] = 2; break;
            case 640:   W[0][2] = p; break;
            case 1024:  W[1][2] = p; break;
            case 1280:  W[2][2] = p; break;
            case 128:   if (w1_n < 3) w1_idx[w1_n++] = idx; break;
            default: break;
        }
    }
    for (int q = 0; q < 3 && q < w1_n; q++)
        W[typeorder[q]][0] = (const float*)d_in[w1_idx[q]];

    // Stage 1: prep
    {
        int jobs = NROWS * NC;
        prep_kernel<<<(jobs + 255) / 256, 256>>>(
            U[0][0], U[1][0], U[2][0],
            U[0][1], U[1][1], U[2][1],
            U[0][2], U[1][2], U[2][2],
            W[0][0], W[0][1], W[0][2],
            W[1][0], W[1][1], W[1][2],
            W[2][0], W[2][1], W[2][2]);
    }

    // Stage 2: transpose A -> At
    transposeA_kernel<<<NB / TAB, 256>>>(A);

    // Stage 3: main contraction
    {
        dim3 grid(NC, NB / (BLK * NBT));
        sc_main_kernel<<<grid, BLK>>>();
    }

    // Stage 4: transpose Ot -> out
    transposeO_kernel<<<NB / TAB, 256>>>((float*)d_out);
}

// round 7
// speedup vs baseline: 1.3023x; 1.3023x over previous
#include <cuda_runtime.h>

// ---------------------------------------------------------------------------
// SymmetricContraction: out[b,c,m] = cubic polynomial in A[b,c,0..8]
// Stage 1 (prep):  S[c][t][m] = sum_k Usym[t][m][k] * w_k[c]
// Stage 2 (trA):   flat permute A[b][c][9] -> At[c][b][12] (writes coalesced)
// Stage 3 (main):  Ot[c][b][12] = sum_t S[c][t][:] * mono_t(At[c][b][:])
// Stage 4 (trO):   flat permute Ot[c][b][12] -> out[b][c][9] (writes coalesced)
// ---------------------------------------------------------------------------

#define NC 128        // channels
#define NB 2048       // nodes
#define NI 9          // irreps dim
#define NIP 12        // padded per-node vector (48B)
#define NT 219        // 9 singles + 45 pairs + 165 triples
#define ROWP 12       // padded S row (floats) -> 48B
#define NBT 2         // nodes per thread
#define BLK 128       // threads per main block

#define NROW2 (45 * 9)
#define NROW3 (165 * 9)
#define NROWS (9 + NROW2 + NROW3)   // 1899 job rows

static __device__ float g_S[NC * NT * ROWP];          // ~1.35 MB
static __device__ float g_At[NC * NB * NIP];          // 12.6 MB
static __device__ float g_Ot[NC * NB * NIP];          // 12.6 MB

// ---------------------------------------------------------------------------
// Kernel 1: fused prep (unchanged — verified)
// ---------------------------------------------------------------------------
__global__ void prep_kernel(
    const float* __restrict__ Us1, const float* __restrict__ Up1, const float* __restrict__ Ud1,
    const float* __restrict__ Us2, const float* __restrict__ Up2, const float* __restrict__ Ud2,
    const float* __restrict__ Us3, const float* __restrict__ Up3, const float* __restrict__ Ud3,
    const float* __restrict__ ws1, const float* __restrict__ ws2, const float* __restrict__ ws3,
    const float* __restrict__ wp1, const float* __restrict__ wp2, const float* __restrict__ wp3,
    const float* __restrict__ wd1, const float* __restrict__ wd2, const float* __restrict__ wd3)
{
    int gid = blockIdx.x * blockDim.x + threadIdx.x;
    if (gid >= NROWS * NC) return;
    int c = gid % NC;
    int row = gid / NC;

    if (row < 9) {
        int t = row;
        float* dst = g_S + (c * NT + t) * ROWP;
        dst[0] = Us1[t] * ws1[c];
#pragma unroll
        for (int m = 0; m < 3; m++) dst[1 + m] = Up1[m * 9 + t] * wp1[c];
#pragma unroll
        for (int m = 0; m < 5; m++) dst[4 + m] = Ud1[m * 9 + t] * wd1[c];
        dst[9] = 0.f; dst[10] = 0.f; dst[11] = 0.f;
        return;
    }

    if (row < 9 + NROW2) {
        int r = row - 9;
        int m = r % 9, tp = r / 9;
        int t = 9 + tp;
        int rem = tp, i = 0, j = 0;
        for (i = 0; i < 9; i++) { int cnt = 9 - i; if (rem < cnt) { j = i + rem; break; } rem -= cnt; }
        float inv = (i == j) ? 0.5f : 1.0f;

        int K; const float* U; const float* w; int mm;
        if (m == 0)      { K = 2; U = Us2; w = ws2; mm = 0; }
        else if (m < 4)  { K = 3; U = Up2; w = wp2; mm = m - 1; }
        else             { K = 4; U = Ud2; w = wd2; mm = m - 4; }

        float s = 0.f;
        for (int k = 0; k < K; k++) {
            float u = U[((mm * 9 + i) * 9 + j) * K + k] + U[((mm * 9 + j) * 9 + i) * K + k];
            s += u * w[k * NC + c];
        }
        float* dst = g_S + (c * NT + t) * ROWP;
        dst[m] = s * inv;
        if (m < 3) dst[9 + m] = 0.f;
        return;
    }

    {
        int r = row - (9 + NROW2);
        int m = r % 9, tp = r / 9;
        int t = 54 + tp;
        int rem = tp, i = 0, j = 0, l = 0;
        for (i = 0; i < 9; i++) { int cnt = (9 - i) * (10 - i) / 2; if (rem < cnt) break; rem -= cnt; }
        for (j = i; j < 9; j++) { int cnt = 9 - j; if (rem < cnt) { l = j + rem; break; } rem -= cnt; }
        float inv;
        if (i == j && j == l)                 inv = 1.0f / 6.0f;
        else if (i == j || j == l || i == l)  inv = 0.5f;
        else                                  inv = 1.0f;

        int K; const float* U; const float* w; int mm;
        if (m == 0)      { K = 5;  U = Us3; w = ws3; mm = 0; }
        else if (m < 4)  { K = 8;  U = Up3; w = wp3; mm = m - 1; }
        else             { K = 10; U = Ud3; w = wd3; mm = m - 4; }

        int P0[6] = { i,i,j,j,l,l }, P1[6] = { j,l,i,l,i,j }, P2i[6] = { l,j,l,i,j,i };
        float s = 0.f;
        for (int k = 0; k < K; k++) {
            float u = 0.f;
#pragma unroll
            for (int p = 0; p < 6; p++)
                u += U[(((mm * 9 + P0[p]) * 9 + P1[p]) * 9 + P2i[p]) * K + k];
            s += u * w[k * NC + c];
        }
        float* dst = g_S + (c * NT + t) * ROWP;
        dst[m] = s * inv;
        if (m < 3) dst[9 + m] = 0.f;
    }
}

// ---------------------------------------------------------------------------
// Kernel 2: flat permute A[b][c][9] -> At[c][b][12].
// gid indexes At (coalesced writes). i>=9 lanes idle (pad never read by main).
// Only one const-div (by 12); b,c splits are shift/mask.
// ---------------------------------------------------------------------------
__global__ __launch_bounds__(256) void trA_kernel(const float* __restrict__ A)
{
    int gid = blockIdx.x * 256 + threadIdx.x;
    if (gid >= NC * NB * NIP) return;
    int i  = gid % NIP;
    int cb = gid / NIP;              // c*NB + b
    if (i < NI) {
        int b = cb & (NB - 1);
        int c = cb >> 11;            // NB = 2048 = 2^11
        g_At[gid] = __ldg(A + (b * NC + c) * NI + i);
    }
}

// ---------------------------------------------------------------------------
// Kernel 3: hot loop (unchanged — verified ~<=17us).
// ---------------------------------------------------------------------------
__device__ __forceinline__ void fma9xN(float acc[NBT][9], const float* __restrict__ row,
                                       const float mN[NBT])
{
    float4 r0 = *reinterpret_cast<const float4*>(row);
    float4 r1 = *reinterpret_cast<const float4*>(row + 4);
    float  r8 = row[8];
#pragma unroll
    for (int n = 0; n < NBT; n++) {
        acc[n][0] = fmaf(r0.x, mN[n], acc[n][0]);
        acc[n][1] = fmaf(r0.y, mN[n], acc[n][1]);
        acc[n][2] = fmaf(r0.z, mN[n], acc[n][2]);
        acc[n][3] = fmaf(r0.w, mN[n], acc[n][3]);
        acc[n][4] = fmaf(r1.x, mN[n], acc[n][4]);
        acc[n][5] = fmaf(r1.y, mN[n], acc[n][5]);
        acc[n][6] = fmaf(r1.z, mN[n], acc[n][6]);
        acc[n][7] = fmaf(r1.w, mN[n], acc[n][7]);
        acc[n][8] = fmaf(r8,  mN[n], acc[n][8]);
    }
}

__global__ __launch_bounds__(BLK) void sc_main_kernel()
{
    __shared__ __align__(16) float sS[NT * ROWP];

    int c = blockIdx.x;
    const float* gS = g_S + c * NT * ROWP;
    for (int idx = threadIdx.x; idx < NT * ROWP; idx += BLK)
        sS[idx] = gS[idx];
    __syncthreads();

    int bbase = blockIdx.y * (BLK * NBT) + threadIdx.x;

    float a[NBT][9];
#pragma unroll
    for (int n = 0; n < NBT; n++) {
        const float4* Ap = reinterpret_cast<const float4*>(
            g_At + (c * NB + bbase + n * BLK) * NIP);
        float4 v0 = Ap[0], v1 = Ap[1], v2 = Ap[2];
        a[n][0] = v0.x; a[n][1] = v0.y; a[n][2] = v0.z; a[n][3] = v0.w;
        a[n][4] = v1.x; a[n][5] = v1.y; a[n][6] = v1.z; a[n][7] = v1.w;
        a[n][8] = v2.x;
    }

    float acc[NBT][9];
#pragma unroll
    for (int n = 0; n < NBT; n++)
#pragma unroll
        for (int q = 0; q < 9; q++) acc[n][q] = 0.f;

#pragma unroll
    for (int i = 0; i < 9; i++) {
        float mN[NBT];
#pragma unroll
        for (int n = 0; n < NBT; n++) mN[n] = a[n][i];
        fma9xN(acc, sS + i * ROWP, mN);
    }

    int trow = 54;
#pragma unroll
    for (int i = 0; i < 9; i++) {
#pragma unroll
        for (int j = i; j < 9; j++) {
            int pidx = i * 9 - (i * (i - 1)) / 2 + (j - i);
            float pN[NBT];
#pragma unroll
            for (int n = 0; n < NBT; n++) pN[n] = a[n][i] * a[n][j];
            fma9xN(acc, sS + (9 + pidx) * ROWP, pN);
#pragma unroll
            for (int l = j; l < 9; l++) {
                float mN[NBT];
#pragma unroll
                for (int n = 0; n < NBT; n++) mN[n] = pN[n] * a[n][l];
                fma9xN(acc, sS + trow * ROWP, mN);
                trow++;
            }
        }
    }

#pragma unroll
    for (int n = 0; n < NBT; n++) {
        float4* op = reinterpret_cast<float4*>(
            g_Ot + (c * NB + bbase + n * BLK) * NIP);
        op[0] = make_float4(acc[n][0], acc[n][1], acc[n][2], acc[n][3]);
        op[1] = make_float4(acc[n][4], acc[n][5], acc[n][6], acc[n][7]);
        op[2] = make_float4(acc[n][8], 0.f, 0.f, 0.f);
    }
}

// ---------------------------------------------------------------------------
// Kernel 4: flat permute Ot[c][b][12] -> out[b][c][9].
// gid indexes out (coalesced writes). One const-div (by 9); splits shift/mask.
// ---------------------------------------------------------------------------
__global__ __launch_bounds__(256) void trO_kernel(float* __restrict__ out)
{
    int gid = blockIdx.x * 256 + threadIdx.x;
    if (gid >= NB * NC * NI) return;
    int i  = gid % NI;
    int bc = gid / NI;               // b*NC + c
    int c = bc & (NC - 1);
    int b = bc >> 7;                 // NC = 128 = 2^7
    out[gid] = g_Ot[(c * NB + b) * NIP + i];
}

// ---------------------------------------------------------------------------
// Launch
// ---------------------------------------------------------------------------
extern "C" void kernel_launch(void* const* d_in, const int* in_sizes, int n_in,
                              void* d_out, int out_size)
{
    const float* A = nullptr;
    const float* U[3][3] = {};
    const float* W[3][3] = {};

    int typeorder[3] = { 0, 1, 2 };
    int to_n = 0;
    int w1_idx[3]; int w1_n = 0;

    for (int idx = 0; idx < n_in; idx++) {
        int s = in_sizes[idx];
        const float* p = (const float*)d_in[idx];
        switch (s) {
            case NB * NC * NI: A = p; break;
            case 9:     U[0][0] = p; break;
            case 162:   U[0][1] = p; break;
            case 3645:  U[0][2] = p; break;
            case 27:    U[1][0] = p; break;
            case 729:   U[1][1] = p; break;
            case 17496: U[1][2] = p; break;
            case 45:    U[2][0] = p; break;
            case 1620:  U[2][1] = p; break;
            case 36450: U[2][2] = p; break;
            case 256:   W[0][1] = p; if (to_n < 3) typeorder[to_n++] = 0; break;
            case 384:   W[1][1] = p; if (to_n < 3) typeorder[to_n++] = 1; break;
            case 512:   W[2][1] = p; if (to_n < 3) typeorder[to_n++] = 2; break;
            case 640:   W[0][2] = p; break;
            case 1024:  W[1][2] = p; break;
            case 1280:  W[2][2] = p; break;
            case 128:   if (w1_n < 3) w1_idx[w1_n++] = idx; break;
            default: break;
        }
    }
    for (int q = 0; q < 3 && q < w1_n; q++)
        W[typeorder[q]][0] = (const float*)d_in[w1_idx[q]];

    // Stage 1: prep
    {
        int jobs = NROWS * NC;
        prep_kernel<<<(jobs + 255) / 256, 256>>>(
            U[0][0], U[1][0], U[2][0],
            U[0][1], U[1][1], U[2][1],
            U[0][2], U[1][2], U[2][2],
            W[0][0], W[0][1], W[0][2],
            W[1][0], W[1][1], W[1][2],
            W[2][0], W[2][1], W[2][2]);
    }

    // Stage 2: permute A -> At
    {
        int n = NC * NB * NIP;
        trA_kernel<<<(n + 255) / 256, 256>>>(A);
    }

    // Stage 3: main contraction
    {
        dim3 grid(NC, NB / (BLK * NBT));
        sc_main_kernel<<<grid, BLK>>>();
    }

    // Stage 4: permute Ot -> out
    {
        int n = NB * NC * NI;
        trO_kernel<<<(n + 255) / 256, 256>>>((float*)d_out);
    }
}